// round 8
// baseline (speedup 1.0000x reference)
#include <cuda_runtime.h>
#include <cstdint>

#define BATCH 8
#define NPTS  4096
#define CH    128
#define KNN   16
#define NDS   2048
#define CAP   96    // per-thread u16 stack capacity
#define HALF  (NPTS / 2)
#define NPAIR (NPTS / 2)

// scratch (allocation-free rule: device globals)
__device__ float g_scores[BATCH * NPTS];
__device__ int   g_idx[BATCH * NDS];

// XLA:GPU small-row reduction order for a 16-element row (shfl_down 8,4,2,1)
__device__ __forceinline__ float tree16(const float* v) {
    float s8[8], s4[4], s2[2];
    #pragma unroll
    for (int l = 0; l < 8; ++l) s8[l] = __fadd_rn(v[l], v[l + 8]);
    #pragma unroll
    for (int l = 0; l < 4; ++l) s4[l] = __fadd_rn(s8[l], s8[l + 4]);
    #pragma unroll
    for (int l = 0; l < 2; ++l) s2[l] = __fadd_rn(s4[l], s4[l + 2]);
    return __fadd_rn(s2[0], s2[1]);
}

// ---- packed f32x2 helpers (each half = full IEEE fp32, RN) ----
__device__ __forceinline__ unsigned long long f32x2_mul(unsigned long long a, unsigned long long b) {
    unsigned long long r; asm("mul.rn.f32x2 %0, %1, %2;" : "=l"(r) : "l"(a), "l"(b)); return r;
}
__device__ __forceinline__ unsigned long long f32x2_add(unsigned long long a, unsigned long long b) {
    unsigned long long r; asm("add.rn.f32x2 %0, %1, %2;" : "=l"(r) : "l"(a), "l"(b)); return r;
}
__device__ __forceinline__ unsigned long long f32x2_fma(unsigned long long a, unsigned long long b,
                                                        unsigned long long c) {
    unsigned long long r; asm("fma.rn.f32x2 %0, %1, %2, %3;" : "=l"(r) : "l"(a), "l"(b), "l"(c)); return r;
}
__device__ __forceinline__ unsigned long long f32x2_rep(float v) {
    unsigned long long r; asm("mov.b64 %0, {%1, %1};" : "=l"(r) : "f"(v)); return r;
}
__device__ __forceinline__ void f32x2_unpack(float& lo, float& hi, unsigned long long v) {
    asm("mov.b64 {%0, %1}, %2;" : "=f"(lo), "=f"(hi) : "l"(v));
}

// Sentinel = mapped(+inf) in high word: unmaps back to +inf.
#define SENTINEL 0xFF800000FFFFFFFFull

// ---------------------------------------------------------------------------
// Kernel 1: per-point KNN score. TWO threads per query (candidate halves).
// Candidates in smem pair-packed SoA: A[j]={x2j,x2j+1,y2j,y2j+1},
// Bz[j]={z2j,z2j+1,sq2j,sq2j+1} -> ld.shared.v2.u64 feeds f32x2 math directly.
// Hot loop computes d2 for TWO candidates per packed instruction with the
// exact per-half op sequence of the verified kernel (bit-identical d2).
// Selection: strict d2<thr filter -> predicated u16 stack -> rare exact flush
// (u64 (mapped_d2,idx) carry chain in registers, sorted ascending).
// ---------------------------------------------------------------------------
__global__ void __launch_bounds__(256) knn_score_kernel(const float* __restrict__ x) {
    extern __shared__ unsigned char smem[];
    float* Af = (float*)smem;                                    // 32KB packed x/y
    float* Bf = (float*)(smem + NPAIR * 16);                     // 32KB packed z/sq
    const ulonglong2* A  = (const ulonglong2*)Af;
    const ulonglong2* Bz = (const ulonglong2*)Bf;
    unsigned short* stk = (unsigned short*)(smem + 2 * NPAIR * 16);  // 48KB

    const int b   = blockIdx.y;
    const int tid = threadIdx.x;
    const int qt  = tid & 127;     // query slot within block
    const int h   = tid >> 7;      // candidate half
    const float* xb = x + b * 3 * NPTS;

    for (int m = tid; m < NPTS; m += 256) {
        float v0 = xb[m], v1 = xb[NPTS + m], v2 = xb[2 * NPTS + m];
        float sq = __fadd_rn(__fadd_rn(__fmul_rn(v0, v0), __fmul_rn(v1, v1)),
                             __fmul_rn(v2, v2));
        int j4 = (m >> 1) * 4 + (m & 1);
        Af[j4] = v0; Af[j4 + 2] = v1;
        Bf[j4] = v2; Bf[j4 + 2] = sq;
    }
    __syncthreads();

    auto loadPt = [&](int m) -> float4 {
        int j4 = (m >> 1) * 4 + (m & 1);
        float4 p;
        p.x = Af[j4]; p.y = Af[j4 + 2];
        p.z = Bf[j4]; p.w = Bf[j4 + 2];
        return p;
    };

    const int q = blockIdx.x * 128 + qt;
    const float4 me = loadPt(q);
    const unsigned long long mex2 = f32x2_rep(me.x);
    const unsigned long long mey2 = f32x2_rep(me.y);
    const unsigned long long mez2 = f32x2_rep(me.z);
    const unsigned long long mew2 = f32x2_rep(me.w);
    const unsigned long long neg2 = f32x2_rep(-2.0f);

    unsigned long long arr[KNN];
    #pragma unroll
    for (int k = 0; k < KNN; ++k) arr[k] = SENTINEL;
    float thrF = __int_as_float(0x7f800000);  // +inf
    int cnt = 0;

    auto flush = [&]() {
        for (int j = 0; j < cnt; ++j) {
            int m = stk[j * 256 + tid];
            float4 p = loadPt(m);
            float inner = fmaf(me.z, p.z, fmaf(me.y, p.y, __fmul_rn(me.x, p.x)));
            float t  = __fadd_rn(me.w, p.w);
            float d2 = fmaf(-2.0f, inner, t);
            unsigned int ub = __float_as_uint(d2);
            ub ^= ((unsigned int)(((int)ub) >> 31)) | 0x80000000u;
            unsigned long long carry = ((unsigned long long)ub << 32) | (unsigned int)m;
            #pragma unroll
            for (int i = 0; i < KNN; ++i) {
                bool c = carry < arr[i];
                unsigned long long lo = c ? carry : arr[i];
                carry                 = c ? arr[i] : carry;
                arr[i] = lo;
            }
        }
        cnt = 0;
        unsigned int hb = (unsigned int)(arr[KNN - 1] >> 32);
        unsigned int uf = (hb & 0x80000000u) ? (hb ^ 0x80000000u) : ~hb;  // unmap
        thrF = __uint_as_float(uf);
    };

    const int pbeg = h * (NPAIR / 2);  // pair index range for this half
    for (int base = 0; base < NPAIR / 2; base += 32) {        // 32 pairs = 64 candidates
        if (__any_sync(0xffffffffu, cnt > (CAP - 64))) flush();
        #pragma unroll 4
        for (int pp = 0; pp < 32; ++pp) {
            int j = pbeg + base + pp;
            ulonglong2 a  = A[j];    // (x0,x1),(y0,y1)
            ulonglong2 zz = Bz[j];   // (z0,z1),(sq0,sq1)
            unsigned long long inner =
                f32x2_fma(mez2, zz.x, f32x2_fma(mey2, a.y, f32x2_mul(mex2, a.x)));
            unsigned long long t2 = f32x2_add(mew2, zz.y);
            unsigned long long d2 = f32x2_fma(neg2, inner, t2);
            float d0, d1;
            f32x2_unpack(d0, d1, d2);
            // strict: equal d2 -> new index larger -> ranks after -> skip
            if (d0 < thrF) { stk[cnt * 256 + tid] = (unsigned short)(2 * j);     ++cnt; }
            if (d1 < thrF) { stk[cnt * 256 + tid] = (unsigned short)(2 * j + 1); ++cnt; }
        }
    }
    flush();

    // merge: half-1 publishes its 16 keys, half-0 inserts them (exact union)
    unsigned long long* mrg = (unsigned long long*)stk;  // reuse (16KB of 48KB)
    __syncthreads();
    if (h == 1) {
        #pragma unroll
        for (int k = 0; k < KNN; ++k) mrg[k * 128 + qt] = arr[k];
    }
    __syncthreads();
    if (h == 0) {
        #pragma unroll
        for (int k = 0; k < KNN; ++k) {
            unsigned long long carry = mrg[k * 128 + qt];
            #pragma unroll
            for (int i = 0; i < KNN; ++i) {
                bool c = carry < arr[i];
                unsigned long long lo = c ? carry : arr[i];
                carry                 = c ? arr[i] : carry;
                arr[i] = lo;
            }
        }

        // arr sorted ascending by (d2, idx) == lax.top_k(-d2) order
        float4 nb[KNN];
        #pragma unroll
        for (int k = 0; k < KNN; ++k) nb[k] = loadPt((unsigned int)arr[k]);

        // score: reduce k first (tree16 per coordinate), then sequentially over d
        float vx[KNN], vy[KNN], vz[KNN];
        #pragma unroll
        for (int k = 0; k < KNN; ++k) {
            float tx = __fsub_rn(nb[k].x, me.x);
            float ty = __fsub_rn(nb[k].y, me.y);
            float tz = __fsub_rn(nb[k].z, me.z);
            vx[k] = __fmul_rn(tx, tx);
            vy[k] = __fmul_rn(ty, ty);
            vz[k] = __fmul_rn(tz, tz);
        }
        float score = __fadd_rn(__fadd_rn(tree16(vx), tree16(vy)), tree16(vz));
        g_scores[b * NPTS + q] = score;
    }
}

// ---------------------------------------------------------------------------
// Kernel 2: per-batch bitonic sort of 4096 keys, compact pair indexing.
// key = (~mapped(score) << 32) | idx -> ascending u64 = desired rank order.
// ---------------------------------------------------------------------------
__global__ void __launch_bounds__(1024) sort_kernel() {
    __shared__ unsigned long long sh[NPTS];
    const int b = blockIdx.x, tid = threadIdx.x;

    for (int i = tid; i < NPTS; i += 1024) {
        unsigned int ub = __float_as_uint(g_scores[b * NPTS + i]);
        ub ^= ((unsigned int)(((int)ub) >> 31)) | 0x80000000u;
        sh[i] = (((unsigned long long)(~ub)) << 32) | (unsigned int)i;
    }
    __syncthreads();

    for (int k = 2; k <= NPTS; k <<= 1) {
        for (int j = k >> 1; j > 0; j >>= 1) {
            #pragma unroll 2
            for (int p = tid; p < NPTS / 2; p += 1024) {
                int i = ((p & ~(j - 1)) << 1) | (p & (j - 1));
                int l = i | j;
                unsigned long long Av = sh[i], Bv = sh[l];
                bool up = ((i & k) == 0);
                if ((Av > Bv) == up) { sh[i] = Bv; sh[l] = Av; }
            }
            __syncthreads();
        }
    }
    for (int j = tid; j < NDS; j += 1024)
        g_idx[b * NDS + j] = (int)(unsigned int)sh[j];
}

// ---------------------------------------------------------------------------
// Kernel 3: gather. out = [xyz (8*3*2048) | points (8*128*2048)]
// ---------------------------------------------------------------------------
__global__ void gather_kernel(const float* __restrict__ x,
                              const float* __restrict__ y,
                              float* __restrict__ out) {
    int t = blockIdx.x * blockDim.x + threadIdx.x;
    const int XYZ = BATCH * 3 * NDS;
    if (t < XYZ) {
        int j = t % NDS;
        int rest = t / NDS;
        int d = rest % 3;
        int b = rest / 3;
        int src = g_idx[b * NDS + j];
        out[t] = x[(b * 3 + d) * NPTS + src];
    } else {
        int t2 = t - XYZ;
        if (t2 < BATCH * CH * NDS) {
            int j = t2 % NDS;
            int rest = t2 / NDS;
            int c = rest % CH;
            int b = rest / CH;
            int src = g_idx[b * NDS + j];
            out[XYZ + t2] = y[(b * CH + c) * NPTS + src];
        }
    }
}

extern "C" void kernel_launch(void* const* d_in, const int* in_sizes, int n_in,
                              void* d_out, int out_size) {
    const float* x = (const float*)d_in[0];
    const float* y = (const float*)d_in[1];
    float* out = (float*)d_out;

    static const size_t kSmem = 2 * NPAIR * 16 + CAP * 256 * 2;  // 112KB
    cudaFuncSetAttribute(knn_score_kernel,
                         cudaFuncAttributeMaxDynamicSharedMemorySize, (int)kSmem);

    dim3 gridA(NPTS / 128, BATCH);
    knn_score_kernel<<<gridA, 256, kSmem>>>(x);
    sort_kernel<<<BATCH, 1024>>>();

    const int total = BATCH * 3 * NDS + BATCH * CH * NDS;
    gather_kernel<<<(total + 255) / 256, 256>>>(x, y, out);
}

// round 9
// speedup vs baseline: 1.1652x; 1.1652x over previous
#include <cuda_runtime.h>
#include <cstdint>

#define BATCH 8
#define NPTS  4096
#define CH    128
#define KNN   16
#define NDS   2048
#define CAP   96    // per-thread u16 stack capacity
#define HALF  (NPTS / 2)

// scratch (allocation-free rule: device globals)
__device__ float g_scores[BATCH * NPTS];
__device__ int   g_idx[BATCH * NDS];

// XLA:GPU small-row reduction order for a 16-element row (shfl_down 8,4,2,1)
__device__ __forceinline__ float tree16(const float* v) {
    float s8[8], s4[4], s2[2];
    #pragma unroll
    for (int l = 0; l < 8; ++l) s8[l] = __fadd_rn(v[l], v[l + 8]);
    #pragma unroll
    for (int l = 0; l < 4; ++l) s4[l] = __fadd_rn(s8[l], s8[l + 4]);
    #pragma unroll
    for (int l = 0; l < 2; ++l) s2[l] = __fadd_rn(s4[l], s4[l + 2]);
    return __fadd_rn(s2[0], s2[1]);
}

// Sentinel = mapped(+inf) in high word: unmaps back to +inf.
#define SENTINEL 0xFF800000FFFFFFFFull

// ---------------------------------------------------------------------------
// Kernel 1: per-point KNN score. TWO threads per query (candidate halves).
// Candidates in smem as float4 (x,y,z,sq). Hot loop is STRAIGHT-LINE and
// branchless: d2 (exact, verified op sequence) -> unconditional STS of the
// candidate index into this thread's stack slot, conditional advance of the
// stack counter (cnt += pred). A slot is only live once cnt advances past it,
// so overwrites by rejected candidates are harmless. Exact top-16 selection
// (sorted u64 (mapped_d2,idx) carry chain in registers) runs only in rare
// flushes over the stacked indices; halves merged exactly at the end.
// ---------------------------------------------------------------------------
__global__ void __launch_bounds__(256) knn_score_kernel(const float* __restrict__ x) {
    extern __shared__ unsigned char smem[];
    float4* pts = (float4*)smem;                                   // 64KB
    unsigned short* stk = (unsigned short*)(smem + NPTS * 16);     // 48KB

    const int b   = blockIdx.y;
    const int tid = threadIdx.x;
    const int qt  = tid & 127;     // query slot within block
    const int h   = tid >> 7;      // candidate half
    const float* xb = x + b * 3 * NPTS;

    for (int m = tid; m < NPTS; m += 256) {
        float v0 = xb[m], v1 = xb[NPTS + m], v2 = xb[2 * NPTS + m];
        float sq = __fadd_rn(__fadd_rn(__fmul_rn(v0, v0), __fmul_rn(v1, v1)),
                             __fmul_rn(v2, v2));
        pts[m] = make_float4(v0, v1, v2, sq);
    }
    __syncthreads();

    const int q = blockIdx.x * 128 + qt;
    const float4 me = pts[q];

    unsigned long long arr[KNN];
    #pragma unroll
    for (int k = 0; k < KNN; ++k) arr[k] = SENTINEL;
    float thrF = __int_as_float(0x7f800000);  // +inf
    int cnt = 0;

    auto flush = [&]() {
        for (int j = 0; j < cnt; ++j) {
            int m = stk[j * 256 + tid];
            float4 p = pts[m];
            float inner = fmaf(me.z, p.z, fmaf(me.y, p.y, __fmul_rn(me.x, p.x)));
            float t  = __fadd_rn(me.w, p.w);
            float d2 = fmaf(-2.0f, inner, t);
            unsigned int ub = __float_as_uint(d2);
            ub ^= ((unsigned int)(((int)ub) >> 31)) | 0x80000000u;
            unsigned long long carry = ((unsigned long long)ub << 32) | (unsigned int)m;
            #pragma unroll
            for (int i = 0; i < KNN; ++i) {
                bool c = carry < arr[i];
                unsigned long long lo = c ? carry : arr[i];
                carry                 = c ? arr[i] : carry;
                arr[i] = lo;
            }
        }
        cnt = 0;
        unsigned int hb = (unsigned int)(arr[KNN - 1] >> 32);
        unsigned int uf = (hb & 0x80000000u) ? (hb ^ 0x80000000u) : ~hb;  // unmap
        thrF = __uint_as_float(uf);
    };

    const int mbeg = h * HALF;
    for (int base = 0; base < HALF; base += 64) {
        if (__any_sync(0xffffffffu, cnt > (CAP - 64))) flush();
        #pragma unroll 4
        for (int mm = 0; mm < 64; ++mm) {
            int m = mbeg + base + mm;
            float4 p = pts[m];  // broadcast LDS.128
            float inner = fmaf(me.z, p.z, fmaf(me.y, p.y, __fmul_rn(me.x, p.x)));
            float t  = __fadd_rn(me.w, p.w);
            float d2 = fmaf(-2.0f, inner, t);
            // branchless push: unconditional store, conditional advance.
            // strict <: equal d2 -> new index larger -> ranks after -> skip
            stk[cnt * 256 + tid] = (unsigned short)m;
            cnt += (d2 < thrF) ? 1 : 0;
        }
    }
    flush();

    // merge: half-1 publishes its 16 keys, half-0 inserts them (exact union)
    unsigned long long* mrg = (unsigned long long*)stk;  // reuse (16KB of 48KB)
    __syncthreads();
    if (h == 1) {
        #pragma unroll
        for (int k = 0; k < KNN; ++k) mrg[k * 128 + qt] = arr[k];
    }
    __syncthreads();
    if (h == 0) {
        #pragma unroll
        for (int k = 0; k < KNN; ++k) {
            unsigned long long carry = mrg[k * 128 + qt];
            #pragma unroll
            for (int i = 0; i < KNN; ++i) {
                bool c = carry < arr[i];
                unsigned long long lo = c ? carry : arr[i];
                carry                 = c ? arr[i] : carry;
                arr[i] = lo;
            }
        }

        // arr sorted ascending by (d2, idx) == lax.top_k(-d2) order
        float4 nb[KNN];
        #pragma unroll
        for (int k = 0; k < KNN; ++k) nb[k] = pts[(unsigned int)arr[k]];

        // score: reduce k first (tree16 per coordinate), then sequentially over d
        float vx[KNN], vy[KNN], vz[KNN];
        #pragma unroll
        for (int k = 0; k < KNN; ++k) {
            float tx = __fsub_rn(nb[k].x, me.x);
            float ty = __fsub_rn(nb[k].y, me.y);
            float tz = __fsub_rn(nb[k].z, me.z);
            vx[k] = __fmul_rn(tx, tx);
            vy[k] = __fmul_rn(ty, ty);
            vz[k] = __fmul_rn(tz, tz);
        }
        float score = __fadd_rn(__fadd_rn(tree16(vx), tree16(vy)), tree16(vz));
        g_scores[b * NPTS + q] = score;
    }
}

// ---------------------------------------------------------------------------
// Kernel 2: per-batch bitonic sort of 4096 keys, compact pair indexing.
// key = (~mapped(score) << 32) | idx -> ascending u64 = desired rank order.
// ---------------------------------------------------------------------------
__global__ void __launch_bounds__(1024) sort_kernel() {
    __shared__ unsigned long long sh[NPTS];
    const int b = blockIdx.x, tid = threadIdx.x;

    for (int i = tid; i < NPTS; i += 1024) {
        unsigned int ub = __float_as_uint(g_scores[b * NPTS + i]);
        ub ^= ((unsigned int)(((int)ub) >> 31)) | 0x80000000u;
        sh[i] = (((unsigned long long)(~ub)) << 32) | (unsigned int)i;
    }
    __syncthreads();

    for (int k = 2; k <= NPTS; k <<= 1) {
        for (int j = k >> 1; j > 0; j >>= 1) {
            #pragma unroll 2
            for (int p = tid; p < NPTS / 2; p += 1024) {
                int i = ((p & ~(j - 1)) << 1) | (p & (j - 1));
                int l = i | j;
                unsigned long long Av = sh[i], Bv = sh[l];
                bool up = ((i & k) == 0);
                if ((Av > Bv) == up) { sh[i] = Bv; sh[l] = Av; }
            }
            __syncthreads();
        }
    }
    for (int j = tid; j < NDS; j += 1024)
        g_idx[b * NDS + j] = (int)(unsigned int)sh[j];
}

// ---------------------------------------------------------------------------
// Kernel 3: gather. out = [xyz (8*3*2048) | points (8*128*2048)]
// ---------------------------------------------------------------------------
__global__ void gather_kernel(const float* __restrict__ x,
                              const float* __restrict__ y,
                              float* __restrict__ out) {
    int t = blockIdx.x * blockDim.x + threadIdx.x;
    const int XYZ = BATCH * 3 * NDS;
    if (t < XYZ) {
        int j = t % NDS;
        int rest = t / NDS;
        int d = rest % 3;
        int b = rest / 3;
        int src = g_idx[b * NDS + j];
        out[t] = x[(b * 3 + d) * NPTS + src];
    } else {
        int t2 = t - XYZ;
        if (t2 < BATCH * CH * NDS) {
            int j = t2 % NDS;
            int rest = t2 / NDS;
            int c = rest % CH;
            int b = rest / CH;
            int src = g_idx[b * NDS + j];
            out[XYZ + t2] = y[(b * CH + c) * NPTS + src];
        }
    }
}

extern "C" void kernel_launch(void* const* d_in, const int* in_sizes, int n_in,
                              void* d_out, int out_size) {
    const float* x = (const float*)d_in[0];
    const float* y = (const float*)d_in[1];
    float* out = (float*)d_out;

    static const size_t kSmem = NPTS * 16 + CAP * 256 * 2;  // 112KB
    cudaFuncSetAttribute(knn_score_kernel,
                         cudaFuncAttributeMaxDynamicSharedMemorySize, (int)kSmem);

    dim3 gridA(NPTS / 128, BATCH);
    knn_score_kernel<<<gridA, 256, kSmem>>>(x);
    sort_kernel<<<BATCH, 1024>>>();

    const int total = BATCH * 3 * NDS + BATCH * CH * NDS;
    gather_kernel<<<(total + 255) / 256, 256>>>(x, y, out);
}